// round 8
// baseline (speedup 1.0000x reference)
#include <cuda_runtime.h>
#include <cstdint>

#define N_NODES 100000
#define D_FEAT 64
#define H_DIM 128
#define MLP_T 352                 // 11 warps
#define SF_PITCH 353              // odd pitch: conflict-free transpose writes

typedef unsigned long long ull;

__device__ float g_flow[N_NODES * D_FEAT];
__device__ int g_is64;

// ---------------- packed f32x2 helpers ----------------
__device__ __forceinline__ ull f2pack(float lo, float hi) {
    ull r; asm("mov.b64 %0,{%1,%2};" : "=l"(r) : "f"(lo), "f"(hi)); return r;
}
__device__ __forceinline__ ull f2splat(float x) {
    ull r; asm("mov.b64 %0,{%1,%1};" : "=l"(r) : "f"(x)); return r;
}
__device__ __forceinline__ void f2unpack(ull v, float& lo, float& hi) {
    asm("mov.b64 {%0,%1},%2;" : "=f"(lo), "=f"(hi) : "l"(v));
}
__device__ __forceinline__ ull f2fma(ull a, ull b, ull c) {
    ull d; asm("fma.rn.f32x2 %0,%1,%2,%3;" : "=l"(d) : "l"(a), "l"(b), "l"(c));
    return d;
}

// ---------------------------------------------------------------------------
// int64 vs int32 edge_index detection (node ids < 2^31 -> high words all 0)
// ---------------------------------------------------------------------------
__global__ void detect_kernel(const int* __restrict__ ei) {
    if (threadIdx.x == 0 && blockIdx.x == 0) {
        int ok = 1;
        for (int i = 0; i < 512; ++i)
            if (ei[2 * i + 1] != 0) { ok = 0; break; }
        g_is64 = ok;
    }
}

__global__ void zero_kernel() {
    int i = blockIdx.x * blockDim.x + threadIdx.x;
    const int n = (N_NODES * D_FEAT) / 4;
    if (i < n)
        reinterpret_cast<float4*>(g_flow)[i] = make_float4(0.f, 0.f, 0.f, 0.f);
}

// ---------------------------------------------------------------------------
// Scatter: 16 threads/edge, one float4 each, red.global.add.v4.f32 to both
// endpoints. edge_attr read with ld.global.cs (streaming / evict-first) so
// the 410MB stream doesn't evict the hot 25.6MB flow region out of L2.
// ---------------------------------------------------------------------------
__global__ void scatter_kernel(const float4* __restrict__ ea,
                               const void* __restrict__ eidx, int E) {
    long long tid = (long long)blockIdx.x * blockDim.x + threadIdx.x;
    int e = (int)(tid >> 4);
    int q = (int)(tid & 15);
    if (e >= E) return;

    long long a, b;
    if (g_is64) {
        const long long* x = (const long long*)eidx;
        a = x[e];
        b = x[E + e];
    } else {
        const int* x = (const int*)eidx;
        a = (long long)x[e];
        b = (long long)x[E + e];
    }

    float4 v = __ldcs(ea + (long long)e * 16 + q);

    float* p0 = &g_flow[a * 64 + q * 4];
    float* p1 = &g_flow[b * 64 + q * 4];
    asm volatile("red.global.add.v4.f32 [%0], {%1,%2,%3,%4};"
                 :: "l"(p0), "f"(v.x), "f"(v.y), "f"(v.z), "f"(v.w) : "memory");
    asm volatile("red.global.add.v4.f32 [%0], {%1,%2,%3,%4};"
                 :: "l"(p1), "f"(v.x), "f"(v.y), "f"(v.z), "f"(v.w) : "memory");
}

// ---------------------------------------------------------------------------
// Fused MLP with packed fma.rn.f32x2 (FFMA2).
// One node per thread, 352 threads/block (11 warps).
// Phase 1 vectorized over hidden pairs (splat fl[d], 8 hidden per group).
// Phase 2 vectorized over output pairs (splat h_k, W2 pairs contiguous).
// SMEM (floats): sW1[8192] | sW2[8192] | sb1[128] | sb2[64] | sF[64*353]
// ---------------------------------------------------------------------------
__global__ __launch_bounds__(MLP_T, 1) void mlp_kernel(
    const float* __restrict__ W1, const float* __restrict__ b1,
    const float* __restrict__ W2, const float* __restrict__ b2,
    float* __restrict__ out) {
    extern __shared__ float sm[];
    float* sW1 = sm;             // 8192
    float* sW2 = sm + 8192;      // 8192
    float* sb1 = sm + 16384;     // 128
    float* sb2 = sm + 16512;     // 64
    float* sF  = sm + 16576;     // 64 * 353

    const int tid = threadIdx.x;
    const int node0 = blockIdx.x * MLP_T;
    const int nNodes = min(MLP_T, N_NODES - node0);

    for (int i = tid; i < 8192; i += MLP_T) sW1[i] = W1[i];
    for (int i = tid; i < 8192; i += MLP_T) sW2[i] = W2[i];
    if (tid < 128) sb1[tid] = b1[tid];
    if (tid < 64)  sb2[tid] = b2[tid];
    // Coalesced flow tile load, stored transposed sF[d][n] (odd pitch).
    for (int i = tid; i < nNodes * 64; i += MLP_T) {
        int n = i >> 6, d = i & 63;
        sF[d * SF_PITCH + n] = g_flow[(long long)(node0 + n) * 64 + d];
    }
    __syncthreads();

    const bool active = (tid < nNodes);
    float fl[64];
    #pragma unroll
    for (int d = 0; d < 64; ++d) fl[d] = active ? sF[d * SF_PITCH + tid] : 0.f;

    ull acc[32];
    #pragma unroll
    for (int o = 0; o < 32; ++o) acc[o] = 0ull;

    #pragma unroll 1
    for (int g = 0; g < 16; ++g) {
        const int j0 = g * 8;
        // ---- phase 1: 8 hidden units as 4 packed accumulators ----
        ull h01 = f2pack(sb1[j0 + 0], sb1[j0 + 1]);
        ull h23 = f2pack(sb1[j0 + 2], sb1[j0 + 3]);
        ull h45 = f2pack(sb1[j0 + 4], sb1[j0 + 5]);
        ull h67 = f2pack(sb1[j0 + 6], sb1[j0 + 7]);
        #pragma unroll
        for (int d = 0; d < 64; ++d) {
            ull fd2 = f2splat(fl[d]);
            const ulonglong2* wp =
                reinterpret_cast<const ulonglong2*>(&sW1[d * 128 + j0]);
            ulonglong2 wa = wp[0];
            ulonglong2 wb = wp[1];
            h01 = f2fma(fd2, wa.x, h01);
            h23 = f2fma(fd2, wa.y, h23);
            h45 = f2fma(fd2, wb.x, h45);
            h67 = f2fma(fd2, wb.y, h67);
        }
        float hs[8];
        f2unpack(h01, hs[0], hs[1]);
        f2unpack(h23, hs[2], hs[3]);
        f2unpack(h45, hs[4], hs[5]);
        f2unpack(h67, hs[6], hs[7]);
        #pragma unroll
        for (int k = 0; k < 8; ++k) hs[k] = fmaxf(hs[k], 0.f);

        // ---- phase 2: accumulate into 32 packed output pairs ----
        #pragma unroll
        for (int k = 0; k < 8; ++k) {
            ull hk2 = f2splat(hs[k]);
            const ulonglong2* w2p =
                reinterpret_cast<const ulonglong2*>(&sW2[(j0 + k) * 64]);
            #pragma unroll
            for (int o = 0; o < 16; ++o) {
                ulonglong2 w = w2p[o];
                acc[2 * o]     = f2fma(hk2, w.x, acc[2 * o]);
                acc[2 * o + 1] = f2fma(hk2, w.y, acc[2 * o + 1]);
            }
        }
    }

    // Column-private writeback into sF, then coalesced transposed store.
    if (active) {
        #pragma unroll
        for (int o = 0; o < 32; ++o) {
            float a0, a1;
            f2unpack(acc[o], a0, a1);
            sF[(2 * o) * SF_PITCH + tid]     = a0 + sb2[2 * o];
            sF[(2 * o + 1) * SF_PITCH + tid] = a1 + sb2[2 * o + 1];
        }
    }
    __syncthreads();
    for (int i = tid; i < nNodes * 64; i += MLP_T) {
        int n = i >> 6, d = i & 63;
        out[(long long)(node0 + n) * 64 + d] = sF[d * SF_PITCH + n];
    }
}

// ---------------------------------------------------------------------------
// Launch
// ---------------------------------------------------------------------------
extern "C" void kernel_launch(void* const* d_in, const int* in_sizes, int n_in,
                              void* d_out, int out_size) {
    int iEI = -1, iEA = -1, iW1 = -1, iW2 = -1, iB1 = -1, iB2 = -1;
    for (int i = 0; i < n_in; ++i) {
        int s = in_sizes[i];
        if (s == 3200000) iEI = i;
        else if (s == 102400000) iEA = i;
        else if (s == 8192) { if (iW1 < 0) iW1 = i; else iW2 = i; }
        else if (s == 128) iB1 = i;
        else if (s == 64)  iB2 = i;
    }
    const int E = in_sizes[iEI] / 2;

    const int smem_bytes = (16576 + 64 * SF_PITCH) * 4;   // 156,672 B
    cudaFuncSetAttribute(mlp_kernel, cudaFuncAttributeMaxDynamicSharedMemorySize,
                         smem_bytes);

    detect_kernel<<<1, 32>>>((const int*)d_in[iEI]);
    zero_kernel<<<(N_NODES * D_FEAT / 4 + 255) / 256, 256>>>();

    long long total = (long long)E * 16;
    scatter_kernel<<<(int)((total + 255) / 256), 256>>>(
        (const float4*)d_in[iEA], d_in[iEI], E);

    mlp_kernel<<<(N_NODES + MLP_T - 1) / MLP_T, MLP_T, smem_bytes>>>(
        (const float*)d_in[iW1], (const float*)d_in[iB1],
        (const float*)d_in[iW2], (const float*)d_in[iB2], (float*)d_out);
}

// round 13
// speedup vs baseline: 1.0310x; 1.0310x over previous
#include <cuda_runtime.h>
#include <cstdint>

#define N_NODES 100000
#define N_PAD   100224
#define TILE_M  128
#define NTILES  ((N_NODES + TILE_M - 1) / TILE_M)   // 782
#define PITCH   132                                  // aT/hT row pitch (floats)

typedef unsigned long long ull;

__device__ float g_flow[N_PAD * 64];
__device__ int g_is64;

// ---------------- packed f32x2 helpers ----------------
__device__ __forceinline__ ull f2splat(float x) {
    ull r; asm("mov.b64 %0,{%1,%1};" : "=l"(r) : "f"(x)); return r;
}
__device__ __forceinline__ void f2unpack(ull v, float& lo, float& hi) {
    asm("mov.b64 {%0,%1},%2;" : "=f"(lo), "=f"(hi) : "l"(v));
}
__device__ __forceinline__ ull f2pack(float lo, float hi) {
    ull r; asm("mov.b64 %0,{%1,%2};" : "=l"(r) : "f"(lo), "f"(hi)); return r;
}
__device__ __forceinline__ ull f2fma(ull a, ull b, ull c) {
    ull d; asm("fma.rn.f32x2 %0,%1,%2,%3;" : "=l"(d) : "l"(a), "l"(b), "l"(c));
    return d;
}

// ---------------------------------------------------------------------------
__global__ void detect_kernel(const int* __restrict__ ei) {
    if (threadIdx.x == 0 && blockIdx.x == 0) {
        int ok = 1;
        for (int i = 0; i < 512; ++i)
            if (ei[2 * i + 1] != 0) { ok = 0; break; }
        g_is64 = ok;
    }
}

__global__ void zero_kernel() {
    int i = blockIdx.x * blockDim.x + threadIdx.x;
    const int n = (N_PAD * 64) / 4;
    if (i < n)
        reinterpret_cast<float4*>(g_flow)[i] = make_float4(0.f, 0.f, 0.f, 0.f);
}

// ---------------------------------------------------------------------------
// Scatter: 16 threads/edge, red.global.add.v4.f32 to both endpoints.
// ---------------------------------------------------------------------------
__global__ void scatter_kernel(const float4* __restrict__ ea,
                               const void* __restrict__ eidx, int E) {
    long long tid = (long long)blockIdx.x * blockDim.x + threadIdx.x;
    int e = (int)(tid >> 4);
    int q = (int)(tid & 15);
    if (e >= E) return;

    long long a, b;
    if (g_is64) {
        const long long* x = (const long long*)eidx;
        a = x[e]; b = x[E + e];
    } else {
        const int* x = (const int*)eidx;
        a = (long long)x[e]; b = (long long)x[E + e];
    }

    float4 v = __ldcs(ea + (long long)e * 16 + q);
    float* p0 = &g_flow[a * 64 + q * 4];
    float* p1 = &g_flow[b * 64 + q * 4];
    asm volatile("red.global.add.v4.f32 [%0], {%1,%2,%3,%4};"
                 :: "l"(p0), "f"(v.x), "f"(v.y), "f"(v.z), "f"(v.w) : "memory");
    asm volatile("red.global.add.v4.f32 [%0], {%1,%2,%3,%4};"
                 :: "l"(p1), "f"(v.x), "f"(v.y), "f"(v.z), "f"(v.w) : "memory");
}

// ---------------------------------------------------------------------------
// Register-tiled fused MLP GEMM. One CTA = 128 nodes, 256 threads (16x16).
// GEMM1: C1[128,128] = aT^T @ W1 (+b1, relu) ; thread tile 8m x 8h.
// GEMM2: C2[128,64]  = hT^T @ W2 (+b2)       ; thread tile 8m x 4o.
// FFMA2 packs node pairs (A is m-contiguous in aT/hT); B values are splats.
// SMEM (floats):
//   region0 [0, 16896): phase1 aT[64][132] (8448) + sW1[64*128] @8448
//                       phase2 hT[128][132] (16896) overwrites both
//   sW2 @16896 (8192) | b1 @25088 (128) | b2 @25216 (64)   total 25280 fl
// ---------------------------------------------------------------------------
#define SM_FLOATS 25280
#define OFF_W1    8448
#define OFF_W2    16896
#define OFF_B1    25088
#define OFF_B2    25216

__global__ __launch_bounds__(256, 1) void mlp_gemm_kernel(
    const float* __restrict__ W1, const float* __restrict__ b1,
    const float* __restrict__ W2, const float* __restrict__ b2,
    float* __restrict__ out) {
    extern __shared__ float sm[];
    float* aT  = sm;              // [64][PITCH]
    float* sW1 = sm + OFF_W1;     // [64][128]
    float* hT  = sm;              // [128][PITCH] (phase 2)
    float* sW2 = sm + OFF_W2;     // [128][64]
    float* sb1 = sm + OFF_B1;
    float* sb2 = sm + OFF_B2;

    const int tid = threadIdx.x;
    const int tx = tid & 15;      // m group
    const int ty = tid >> 4;      // h / o group
    const int node0 = blockIdx.x * TILE_M;

    // ---- fills ----
    for (int i = tid; i < 8192; i += 256) sW1[i] = W1[i];
    for (int i = tid; i < 8192; i += 256) sW2[i] = W2[i];
    if (tid < 128) sb1[tid] = b1[tid];
    if (tid < 64)  sb2[tid] = b2[tid];
    // aT[d][m] transposed fill from g_flow (rows beyond N_NODES read padded 0s)
    for (int i = tid; i < 2048; i += 256) {
        int r = i >> 4, c4 = (i & 15) * 4;
        float4 v = *reinterpret_cast<const float4*>(
            &g_flow[(long long)(node0 + r) * 64 + c4]);
        aT[(c4 + 0) * PITCH + r] = v.x;
        aT[(c4 + 1) * PITCH + r] = v.y;
        aT[(c4 + 2) * PITCH + r] = v.z;
        aT[(c4 + 3) * PITCH + r] = v.w;
    }
    __syncthreads();

    // ---- GEMM1: acc[p][j], p = m-pair 0..3 (m0+2p, m0+2p+1), j = h 0..7 ----
    const int m0 = tx * 8;
    const int h0 = ty * 8;
    ull acc[4][8];
    #pragma unroll
    for (int j = 0; j < 8; ++j) {
        ull bj = f2splat(sb1[h0 + j]);
        #pragma unroll
        for (int p = 0; p < 4; ++p) acc[p][j] = bj;
    }
    {
        const float* ap = &aT[m0];
        const float* bp = &sW1[h0];
        #pragma unroll 8
        for (int k = 0; k < 64; ++k, ap += PITCH, bp += 128) {
            ulonglong2 a01 = *reinterpret_cast<const ulonglong2*>(ap);
            ulonglong2 a23 = *reinterpret_cast<const ulonglong2*>(ap + 4);
            float4 w0 = *reinterpret_cast<const float4*>(bp);
            float4 w1 = *reinterpret_cast<const float4*>(bp + 4);
            ull bs[8];
            bs[0] = f2splat(w0.x); bs[1] = f2splat(w0.y);
            bs[2] = f2splat(w0.z); bs[3] = f2splat(w0.w);
            bs[4] = f2splat(w1.x); bs[5] = f2splat(w1.y);
            bs[6] = f2splat(w1.z); bs[7] = f2splat(w1.w);
            #pragma unroll
            for (int j = 0; j < 8; ++j) {
                acc[0][j] = f2fma(a01.x, bs[j], acc[0][j]);
                acc[1][j] = f2fma(a01.y, bs[j], acc[1][j]);
                acc[2][j] = f2fma(a23.x, bs[j], acc[2][j]);
                acc[3][j] = f2fma(a23.y, bs[j], acc[3][j]);
            }
        }
    }
    __syncthreads();   // all reads of aT/W1 done before hT overwrites

    // ---- relu + transposed store into hT[h][m] (pair stores) ----
    #pragma unroll
    for (int j = 0; j < 8; ++j) {
        float* row = &hT[(h0 + j) * PITCH + m0];
        #pragma unroll
        for (int p = 0; p < 4; ++p) {
            float x0, x1;
            f2unpack(acc[p][j], x0, x1);
            x0 = fmaxf(x0, 0.f);
            x1 = fmaxf(x1, 0.f);
            *reinterpret_cast<ull*>(row + 2 * p) = f2pack(x0, x1);
        }
    }
    __syncthreads();

    // ---- GEMM2: acc2[p][j], j = o 0..3 ----
    const int o0 = ty * 4;
    ull acc2[4][4];
    #pragma unroll
    for (int j = 0; j < 4; ++j) {
        ull bj = f2splat(sb2[o0 + j]);
        #pragma unroll
        for (int p = 0; p < 4; ++p) acc2[p][j] = bj;
    }
    {
        const float* ap = &hT[m0];
        const float* bp = &sW2[o0];
        #pragma unroll 8
        for (int k = 0; k < 128; ++k, ap += PITCH, bp += 64) {
            ulonglong2 a01 = *reinterpret_cast<const ulonglong2*>(ap);
            ulonglong2 a23 = *reinterpret_cast<const ulonglong2*>(ap + 4);
            float4 w = *reinterpret_cast<const float4*>(bp);
            ull bs[4];
            bs[0] = f2splat(w.x); bs[1] = f2splat(w.y);
            bs[2] = f2splat(w.z); bs[3] = f2splat(w.w);
            #pragma unroll
            for (int j = 0; j < 4; ++j) {
                acc2[0][j] = f2fma(a01.x, bs[j], acc2[0][j]);
                acc2[1][j] = f2fma(a01.y, bs[j], acc2[1][j]);
                acc2[2][j] = f2fma(a23.x, bs[j], acc2[2][j]);
                acc2[3][j] = f2fma(a23.y, bs[j], acc2[3][j]);
            }
        }
    }

    // ---- epilogue: float4 stores, row-guarded ----
    #pragma unroll
    for (int p = 0; p < 4; ++p) {
        int r0 = node0 + m0 + 2 * p;
        float4 lo, hi;
        f2unpack(acc2[p][0], lo.x, hi.x);
        f2unpack(acc2[p][1], lo.y, hi.y);
        f2unpack(acc2[p][2], lo.z, hi.z);
        f2unpack(acc2[p][3], lo.w, hi.w);
        if (r0 < N_NODES)
            *reinterpret_cast<float4*>(&out[(long long)r0 * 64 + o0]) = lo;
        if (r0 + 1 < N_NODES)
            *reinterpret_cast<float4*>(&out[(long long)(r0 + 1) * 64 + o0]) = hi;
    }
}

// ---------------------------------------------------------------------------
extern "C" void kernel_launch(void* const* d_in, const int* in_sizes, int n_in,
                              void* d_out, int out_size) {
    int iEI = -1, iEA = -1, iW1 = -1, iW2 = -1, iB1 = -1, iB2 = -1;
    for (int i = 0; i < n_in; ++i) {
        int s = in_sizes[i];
        if (s == 3200000) iEI = i;
        else if (s == 102400000) iEA = i;
        else if (s == 8192) { if (iW1 < 0) iW1 = i; else iW2 = i; }
        else if (s == 128) iB1 = i;
        else if (s == 64)  iB2 = i;
    }
    const int E = in_sizes[iEI] / 2;

    const int smem_bytes = SM_FLOATS * 4;   // 101,120 B
    cudaFuncSetAttribute(mlp_gemm_kernel,
                         cudaFuncAttributeMaxDynamicSharedMemorySize, smem_bytes);

    detect_kernel<<<1, 32>>>((const int*)d_in[iEI]);
    zero_kernel<<<(N_PAD * 64 / 4 + 255) / 256, 256>>>();

    long long total = (long long)E * 16;
    scatter_kernel<<<(int)((total + 255) / 256), 256>>>(
        (const float4*)d_in[iEA], d_in[iEI], E);

    mlp_gemm_kernel<<<NTILES, 256, smem_bytes>>>(
        (const float*)d_in[iW1], (const float*)d_in[iB1],
        (const float*)d_in[iW2], (const float*)d_in[iB2], (float*)d_out);
}